// round 5
// baseline (speedup 1.0000x reference)
#include <cuda_runtime.h>
#include <cuda_fp16.h>

// LODs = int(16 * (256/16)^(L/7)) = 16, 23, 35, 52, 78, 115, 172, 256
// entries (res^2): 256, 529, 1225, 2704, 6084, 13225, 29584, 65536
// LODs 0-6 in smem as scaled __half2 (53607 * 4B = 214.4KB); LOD7 in L2 (fp32).
// 2 points per thread per iteration for doubled gather MLP.

#define N_LOD 8
#define SMEM_H2 53607
#define SMEM_BYTES (SMEM_H2 * 4)
#define SCALE_UP   1024.0f
#define SCALE_DOWN (1.0f / 1024.0f)
#define TPB 1024
#define PPT 2

__global__ void __launch_bounds__(TPB, 1)
dense_grid_ilp2_kernel(const float2* __restrict__ pts,
                       const float2* __restrict__ cb0,
                       const float2* __restrict__ cb1,
                       const float2* __restrict__ cb2,
                       const float2* __restrict__ cb3,
                       const float2* __restrict__ cb4,
                       const float2* __restrict__ cb5,
                       const float2* __restrict__ cb6,
                       const float2* __restrict__ cb7,
                       float4* __restrict__ out,
                       int n)
{
    extern __shared__ __half2 s[];

    // ---- Stage LODs 0-6 into shared memory as scaled half2 (coalesced) ----
    {
        const float2* __restrict__ srcs[7] = {cb0, cb1, cb2, cb3, cb4, cb5, cb6};
        const int cnt[7] = {256, 529, 1225, 2704, 6084, 13225, 29584};
        const int off[7] = {0, 256, 785, 2010, 4714, 10798, 24023};
#pragma unroll
        for (int L = 0; L < 7; ++L) {
            const float2* src = srcs[L];
            __half2* dst = s + off[L];
            const int c = cnt[L];
            for (int j = threadIdx.x; j < c; j += TPB) {
                const float2 v = __ldg(&src[j]);
                dst[j] = __floats2half2_rn(v.x * SCALE_UP, v.y * SCALE_UP);
            }
        }
    }
    __syncthreads();

    const int RES[N_LOD] = {16, 23, 35, 52, 78, 115, 172, 256};
    const int OFF[7] = {0, 256, 785, 2010, 4714, 10798, 24023};

    const unsigned* sw = (const unsigned*)s;  // raw half2 view

    const int tile = TPB * PPT;
    const int stride = gridDim.x * tile;
    for (int i0 = blockIdx.x * tile + threadIdx.x; i0 < n; i0 += stride) {
        const int i1 = i0 + TPB;
        const bool v1 = (i1 < n);

        // Issue both point loads up front.
        const float2 p0 = __ldg(&pts[i0]);
        const float2 p1 = v1 ? __ldg(&pts[i1]) : p0;

        // Indices for both points (trunc == floor for nonneg; same fp32 mul as ref).
        int ia[N_LOD], ib[N_LOD];
#pragma unroll
        for (int L = 0; L < N_LOD; ++L) {
            const int r = RES[L];
            const float sc = (float)(r - 1);
            ia[L] = (int)(p0.x * sc) + (int)(p0.y * sc) * r;
            ib[L] = (int)(p1.x * sc) + (int)(p1.y * sc) * r;
        }

        // Long-latency L2 gathers for both points first (MLP=2 on the big LOD).
        const float2 ga7 = __ldg(&cb7[ia[7]]);
        const float2 gb7 = __ldg(&cb7[ib[7]]);

        // Shared-memory gathers (raw u32 half2 to limit register pressure).
        unsigned ha[7], hb[7];
#pragma unroll
        for (int L = 0; L < 7; ++L) {
            ha[L] = sw[OFF[L] + ia[L]];
            hb[L] = sw[OFF[L] + ib[L]];
        }

        // ---- Assemble + store point 0 ----
        {
            float2 f[7];
#pragma unroll
            for (int L = 0; L < 7; ++L) {
                const float2 v = __half22float2(*(const __half2*)&ha[L]);
                f[L].x = v.x * SCALE_DOWN;
                f[L].y = v.y * SCALE_DOWN;
            }
            float4* o = out + (size_t)i0 * 4;
            o[0] = make_float4(f[0].x, f[1].x, f[2].x, f[3].x);
            o[1] = make_float4(f[4].x, f[5].x, f[6].x, ga7.x);
            o[2] = make_float4(f[0].y, f[1].y, f[2].y, f[3].y);
            o[3] = make_float4(f[4].y, f[5].y, f[6].y, ga7.y);
        }

        // ---- Assemble + store point 1 ----
        if (v1) {
            float2 f[7];
#pragma unroll
            for (int L = 0; L < 7; ++L) {
                const float2 v = __half22float2(*(const __half2*)&hb[L]);
                f[L].x = v.x * SCALE_DOWN;
                f[L].y = v.y * SCALE_DOWN;
            }
            float4* o = out + (size_t)i1 * 4;
            o[0] = make_float4(f[0].x, f[1].x, f[2].x, f[3].x);
            o[1] = make_float4(f[4].x, f[5].x, f[6].x, gb7.x);
            o[2] = make_float4(f[0].y, f[1].y, f[2].y, f[3].y);
            o[3] = make_float4(f[4].y, f[5].y, f[6].y, gb7.y);
        }
    }
}

extern "C" void kernel_launch(void* const* d_in, const int* in_sizes, int n_in,
                              void* d_out, int out_size)
{
    const float2* pts = (const float2*)d_in[0];
    const float2* cb0 = (const float2*)d_in[1];
    const float2* cb1 = (const float2*)d_in[2];
    const float2* cb2 = (const float2*)d_in[3];
    const float2* cb3 = (const float2*)d_in[4];
    const float2* cb4 = (const float2*)d_in[5];
    const float2* cb5 = (const float2*)d_in[6];
    const float2* cb6 = (const float2*)d_in[7];
    const float2* cb7 = (const float2*)d_in[8];
    float4* out = (float4*)d_out;

    const int n = in_sizes[0] / 2;

    static int configured = -1;
    if (configured < 0) {
        cudaFuncSetAttribute(dense_grid_ilp2_kernel,
                             cudaFuncAttributeMaxDynamicSharedMemorySize,
                             SMEM_BYTES);
        cudaDeviceGetAttribute(&configured, cudaDevAttrMultiProcessorCount, 0);
    }
    const int blocks = configured;  // one persistent block per SM

    dense_grid_ilp2_kernel<<<blocks, TPB, SMEM_BYTES>>>(
        pts, cb0, cb1, cb2, cb3, cb4, cb5, cb6, cb7, out, n);
}

// round 6
// speedup vs baseline: 1.0174x; 1.0174x over previous
#include <cuda_runtime.h>
#include <cuda_fp16.h>

// LODs = int(16 * (256/16)^(L/7)) = 16, 23, 35, 52, 78, 115, 172, 256
// entries (res^2): 256, 529, 1225, 2704, 6084, 13225, 29584, 65536
// LODs 0-5 in smem as scaled __half2 (24023 * 4B = 96.1KB) -> 2 blocks/SM.
// LODs 6,7 from global (L2-resident fp32).

#define N_LOD 8
#define SMEM_H2 24023
#define SMEM_BYTES (SMEM_H2 * 4)
#define SCALE_UP   1024.0f
#define SCALE_DOWN (1.0f / 1024.0f)
#define TPB 1024

__global__ void __launch_bounds__(TPB, 2)
dense_grid_occ_kernel(const float2* __restrict__ pts,
                      const float2* __restrict__ cb0,
                      const float2* __restrict__ cb1,
                      const float2* __restrict__ cb2,
                      const float2* __restrict__ cb3,
                      const float2* __restrict__ cb4,
                      const float2* __restrict__ cb5,
                      const float2* __restrict__ cb6,
                      const float2* __restrict__ cb7,
                      float4* __restrict__ out,
                      int n)
{
    extern __shared__ __half2 s[];

    // ---- Stage LODs 0-5 into shared memory as scaled half2 (coalesced) ----
    {
        const float2* __restrict__ srcs[6] = {cb0, cb1, cb2, cb3, cb4, cb5};
        const int cnt[6] = {256, 529, 1225, 2704, 6084, 13225};
        const int off[6] = {0, 256, 785, 2010, 4714, 10798};
#pragma unroll
        for (int L = 0; L < 6; ++L) {
            const float2* src = srcs[L];
            __half2* dst = s + off[L];
            const int c = cnt[L];
            for (int j = threadIdx.x; j < c; j += TPB) {
                const float2 v = __ldg(&src[j]);
                dst[j] = __floats2half2_rn(v.x * SCALE_UP, v.y * SCALE_UP);
            }
        }
    }
    __syncthreads();

    const int RES[N_LOD] = {16, 23, 35, 52, 78, 115, 172, 256};
    const int OFF[6] = {0, 256, 785, 2010, 4714, 10798};

    const int stride = gridDim.x * TPB;
    for (int i = blockIdx.x * TPB + threadIdx.x; i < n; i += stride) {
        const float2 p = __ldg(&pts[i]);

        int idx[N_LOD];
#pragma unroll
        for (int L = 0; L < N_LOD; ++L) {
            const int r = RES[L];
            const float sc = (float)(r - 1);
            // trunc == floor for nonneg; same single fp32 multiply as reference
            idx[L] = (int)(p.x * sc) + (int)(p.y * sc) * r;
        }

        // Long-latency global gathers first (LODs 6,7 — L2-resident).
        const float2 g6 = __ldg(&cb6[idx[6]]);
        const float2 g7 = __ldg(&cb7[idx[7]]);

        // Shared-memory gathers for LODs 0-5 (scaled half2).
        float2 f[6];
#pragma unroll
        for (int L = 0; L < 6; ++L) {
            const float2 v = __half22float2(s[OFF[L] + idx[L]]);
            f[L].x = v.x * SCALE_DOWN;
            f[L].y = v.y * SCALE_DOWN;
        }

        // Output layout: out[i][feat * 8 + L]; 16 floats = 4 x float4.
        float4* o = out + (size_t)i * 4;
        o[0] = make_float4(f[0].x, f[1].x, f[2].x, f[3].x);
        o[1] = make_float4(f[4].x, f[5].x, g6.x, g7.x);
        o[2] = make_float4(f[0].y, f[1].y, f[2].y, f[3].y);
        o[3] = make_float4(f[4].y, f[5].y, g6.y, g7.y);
    }
}

extern "C" void kernel_launch(void* const* d_in, const int* in_sizes, int n_in,
                              void* d_out, int out_size)
{
    const float2* pts = (const float2*)d_in[0];
    const float2* cb0 = (const float2*)d_in[1];
    const float2* cb1 = (const float2*)d_in[2];
    const float2* cb2 = (const float2*)d_in[3];
    const float2* cb3 = (const float2*)d_in[4];
    const float2* cb4 = (const float2*)d_in[5];
    const float2* cb5 = (const float2*)d_in[6];
    const float2* cb6 = (const float2*)d_in[7];
    const float2* cb7 = (const float2*)d_in[8];
    float4* out = (float4*)d_out;

    const int n = in_sizes[0] / 2;

    static int sm_count = -1;
    if (sm_count < 0) {
        cudaFuncSetAttribute(dense_grid_occ_kernel,
                             cudaFuncAttributeMaxDynamicSharedMemorySize,
                             SMEM_BYTES);
        cudaDeviceGetAttribute(&sm_count, cudaDevAttrMultiProcessorCount, 0);
    }
    const int blocks = sm_count * 2;  // 2 resident blocks per SM -> 64 warps

    dense_grid_occ_kernel<<<blocks, TPB, SMEM_BYTES>>>(
        pts, cb0, cb1, cb2, cb3, cb4, cb5, cb6, cb7, out, n);
}